// round 16
// baseline (speedup 1.0000x reference)
#include <cuda_runtime.h>
#include <math.h>

// Shapes fixed by the problem:
//   hidden_states (8, 4096, 1024) f32, W (1024,1024) f32, b (1024) f32,
//   alpha (1) f32.  Output (8, 1, 1024) f32.
#define BATCH 8
#define SEQ   4096
#define HID   1024
#define NTHREADS 256
#define ROWS_PB  4                       // W rows per block
#define NBLOCKS  (HID / ROWS_PB)         // 256  (all resident in one wave)

// Bit layout (identical for x and W — consistency is all that matters):
//   chunk c, word k (0..3), bit `lane`  <->  element h = c*128 + 4*lane + k

// Scratch (__device__ globals; allocation-free rule).
__device__ uint4 g_xneg[BATCH][8];       // [batch][chunk] 4 sign words
__device__ uint4 g_xnz [BATCH][8];       // [batch][chunk] 4 nonzero words
__device__ float g_wpart[NBLOCKS];       // per-block |W| partials
__device__ unsigned g_arrive = 0;        // barrier arrivals (reset each launch by last arriver)
__device__ unsigned g_gen    = 0;        // release generation (monotonic; value never affects output)

__global__ void __launch_bounds__(NTHREADS)
fused_pooler_kernel(const float* __restrict__ x,
                    const float* __restrict__ Wm,
                    const float* __restrict__ bias,
                    const float* __restrict__ alpha,
                    float* __restrict__ out)
{
    const int tid  = threadIdx.x;
    const int warp = tid >> 5;           // chunk 0..7
    const int lane = tid & 31;
    const int row0 = blockIdx.x * ROWS_PB;
    const int mybatch = lane & 7;        // batch-in-lane

    // Snapshot the release generation BEFORE this block can possibly arrive.
    __shared__ unsigned s_gen0;
    __shared__ float    s_wsum;
    if (tid == 0) s_gen0 = *(volatile unsigned*)&g_gen;
    __syncthreads();

    // ---- Phase 1a: load my 4 W rows into registers (kept across barrier) ----
    float4 wv[ROWS_PB];
    #pragma unroll
    for (int r = 0; r < ROWS_PB; ++r)
        wv[r] = __ldg((const float4*)(Wm + (size_t)(row0 + r) * HID) + warp * 32 + lane);

    // ---- Phase 1b: blocks 0..7 pack x bits for batch = blockIdx ----
    if (blockIdx.x < BATCH) {
        const int b = blockIdx.x;
        float4 v = __ldg((const float4*)(x + (size_t)b * SEQ * HID) + warp * 32 + lane);
        const float e[4] = {v.x, v.y, v.z, v.w};
        unsigned neg[4], nz[4];
        #pragma unroll
        for (int k = 0; k < 4; ++k) {
            neg[k] = __ballot_sync(0xffffffffu, e[k] < 0.0f);
            nz [k] = __ballot_sync(0xffffffffu, e[k] != 0.0f);
        }
        if (lane == 0) {
            g_xneg[b][warp] = make_uint4(neg[0], neg[1], neg[2], neg[3]);
            g_xnz [b][warp] = make_uint4(nz [0], nz [1], nz [2], nz [3]);
        }
    }

    // ---- Phase 1c: |W| partial for my 4 rows ----
    float asum = 0.0f;
    #pragma unroll
    for (int r = 0; r < ROWS_PB; ++r)
        asum += fabsf(wv[r].x) + fabsf(wv[r].y) + fabsf(wv[r].z) + fabsf(wv[r].w);
    #pragma unroll
    for (int off = 16; off > 0; off >>= 1)
        asum += __shfl_xor_sync(0xffffffffu, asum, off);

    __shared__ float s_asum[8];
    if (lane == 0) s_asum[warp] = asum;
    __syncthreads();
    if (tid == 0) {
        float t = 0.0f;
        #pragma unroll
        for (int w2 = 0; w2 < 8; ++w2) t += s_asum[w2];
        g_wpart[blockIdx.x] = t;
    }

    // ---- Grid barrier (all 256 blocks resident => spin is safe) ----
    __threadfence();                      // publish this thread's stores
    __syncthreads();                      // whole block's stores now fenced
    if (tid == 0) {
        unsigned t = atomicAdd(&g_arrive, 1u);
        if (t == NBLOCKS - 1) {
            atomicExch(&g_arrive, 0u);    // reset for next launch/replay
            __threadfence();
            atomicAdd(&g_gen, 1u);        // release
        } else {
            while (*(volatile unsigned*)&g_gen == s_gen0) { __nanosleep(40); }
        }
    }
    __syncthreads();
    __threadfence();                      // acquire side

    // ---- Phase 2: popcount dots on register-held W ----
    const uint4 xn = __ldcg((const uint4*)&g_xneg[mybatch][warp]);   // bypass L1
    const uint4 xz = __ldcg((const uint4*)&g_xnz [mybatch][warp]);
    const unsigned xnega[4] = {xn.x, xn.y, xn.z, xn.w};
    const unsigned xnza [4] = {xz.x, xz.y, xz.z, xz.w};

    int acc[ROWS_PB];
    #pragma unroll
    for (int r = 0; r < ROWS_PB; ++r) {
        const float we[4] = {wv[r].x, wv[r].y, wv[r].z, wv[r].w};
        int a = 0;
        #pragma unroll
        for (int k = 0; k < 4; ++k) {
            unsigned wneg = __ballot_sync(0xffffffffu, we[k] < 0.0f);
            unsigned wnz  = __ballot_sync(0xffffffffu, we[k] != 0.0f);
            unsigned valid = xnza[k] & wnz;
            unsigned diff  = (xnega[k] ^ wneg) & valid;
            a += __popc(valid) - 2 * __popc(diff);
        }
        acc[r] = a;
    }

    __shared__ int s_acc[8][ROWS_PB][BATCH];   // [warp][row][batch]
    if (lane < BATCH) {
        #pragma unroll
        for (int r = 0; r < ROWS_PB; ++r)
            s_acc[warp][r][lane] = acc[r];     // lanes 0-7 carry batches 0-7
    }

    // warp 0: reduce the 256 |W| partials (2 float4 per lane)
    if (warp == 0) {
        float4 p0 = __ldcg((const float4*)g_wpart + lane);
        float4 p1 = __ldcg((const float4*)g_wpart + 32 + lane);
        float ws = p0.x + p0.y + p0.z + p0.w + p1.x + p1.y + p1.z + p1.w;
        #pragma unroll
        for (int off = 16; off > 0; off >>= 1)
            ws += __shfl_xor_sync(0xffffffffu, ws, off);
        if (lane == 0) s_wsum = ws;
    }
    __syncthreads();

    if (tid < 32) {
        const int r = tid >> 3;        // row within block
        const int b = tid & 7;         // batch
        int dot = 0;
        #pragma unroll
        for (int w2 = 0; w2 < 8; ++w2) dot += s_acc[w2][r][b];

        const float wscale = s_wsum * (1.0f / ((float)HID * (float)HID));
        const float a      = fmaxf(__ldg(alpha), 1e-5f);
        const float scale  = a * wscale;
        out[b * HID + row0 + r] = tanhf(scale * (float)dot + __ldg(bias + row0 + r));
    }
}

extern "C" void kernel_launch(void* const* d_in, const int* in_sizes, int n_in,
                              void* d_out, int out_size)
{
    const float* x     = (const float*)d_in[0];
    const float* Wm    = (const float*)d_in[1];
    const float* bias  = (const float*)d_in[2];
    const float* alpha = (const float*)d_in[3];
    float* out = (float*)d_out;

    fused_pooler_kernel<<<NBLOCKS, NTHREADS>>>(x, Wm, bias, alpha, out);
}